// round 13
// baseline (speedup 1.0000x reference)
#include <cuda_runtime.h>
#include <cuda_fp16.h>
#include <cstdint>

// ---------------------------------------------------------------------------
// T=16384, D=H=2880, E=8, C=2048, N1=5760. K=2880 both GEMMs.
// fp16 mma.sync m16n8k16 (fp32 acc), 2 CTAs/SM, __syncthreads pipeline (R10).
// NEW: all fp32->fp16 conversions are folded into GEMM1's timeline:
//   - x and w1 slabs converted cooperatively by the GEMM1 CTAs that need them
//     (atomic chunk claiming + done-counter, deadlock-free, idempotent)
//   - w2 converted by an extra blockIdx.y row of GEMM1 (idle-DRAM overlap)
// ---------------------------------------------------------------------------
#define KDIM 2880
#define BM 128
#define BK 64              // halves per k-stage (128 B rows)
#define NSTAGE 3
#define NKITER 45          // 2880/64
#define LDSH 72            // smem pitch in halves (64 + 8 pad) = 144 B
#define A_BYTES (BM * LDSH * 2)  // 18432
#define NTHR 256
#define NCHUNK 18          // chunks per 128x2880 slab (92160 float4 / 5120)
#define CHSZ 5120

__device__ __half g_xh[(size_t)16384 * 2880];
__device__ __half g_w1h[(size_t)8 * 5760 * 2880];
__device__ __half g_w2h[(size_t)8 * 2880 * 2880];
__device__ __half g_acth[(size_t)16384 * 2880];
// [0,360) w1 claim | [360,720) w1 done | [720,848) x claim | [848,976) x done
__device__ int g_ctr[976];

__global__ void reset_counters_kernel() {
    if (threadIdx.x < 976) g_ctr[threadIdx.x] = 0;
}

__device__ __forceinline__ uint32_t s2u(const void* p) {
    uint32_t a;
    asm("{.reg .u64 t; cvta.to.shared.u64 t, %1; cvt.u32.u64 %0, t;}"
        : "=r"(a) : "l"(p));
    return a;
}
__device__ __forceinline__ void cp16(uint32_t dst, const void* src) {
    asm volatile("cp.async.cg.shared.global [%0], [%1], 16;" ::"r"(dst),
                 "l"(src) : "memory");
}
__device__ __forceinline__ void ldsm_x4(uint32_t* r, uint32_t addr) {
    asm volatile(
        "ldmatrix.sync.aligned.m8n8.x4.shared.b16 {%0,%1,%2,%3}, [%4];"
        : "=r"(r[0]), "=r"(r[1]), "=r"(r[2]), "=r"(r[3]) : "r"(addr));
}
__device__ __forceinline__ void ldsm_x2(uint32_t* r, uint32_t addr) {
    asm volatile(
        "ldmatrix.sync.aligned.m8n8.x2.shared.b16 {%0,%1}, [%2];"
        : "=r"(r[0]), "=r"(r[1]) : "r"(addr));
}
__device__ __forceinline__ void mma_f16(float* c, const uint32_t* a,
                                        const uint32_t* b) {
    asm volatile(
        "mma.sync.aligned.m16n8k16.row.col.f32.f16.f16.f32 "
        "{%0,%1,%2,%3}, {%4,%5,%6,%7}, {%8,%9}, {%0,%1,%2,%3};"
        : "+f"(c[0]), "+f"(c[1]), "+f"(c[2]), "+f"(c[3])
        : "r"(a[0]), "r"(a[1]), "r"(a[2]), "r"(a[3]), "r"(b[0]), "r"(b[1]));
}

// Cooperative slab conversion: all CTAs sharing a slab claim chunks until
// exhausted; each completed chunk bumps the done counter. Deadlock-free.
__device__ void convert_slab(const float4* __restrict__ src,
                             __half2* __restrict__ dst, int* claim, int* done,
                             int tid, int* s_chunk) {
    for (;;) {
        __syncthreads();
        if (tid == 0) *s_chunk = atomicAdd(claim, 1);
        __syncthreads();
        const int c = *s_chunk;
        if (c >= NCHUNK) break;
        for (int i = c * CHSZ + tid; i < (c + 1) * CHSZ; i += NTHR) {
            float4 v = src[i];
            dst[2 * i] = __floats2half2_rn(v.x, v.y);
            dst[2 * i + 1] = __floats2half2_rn(v.z, v.w);
        }
        __syncthreads();
        if (tid == 0) {
            __threadfence();
            atomicAdd(done, 1);
        }
    }
}

// ---------------------------------------------------------------------------
// NT = n8-subtiles per warp. BN = 32*NT. NT=4 -> 128 (GEMM1), 3 -> 96 (GEMM2)
// ---------------------------------------------------------------------------
template <bool SWIGLU, int NT>
__global__ __launch_bounds__(NTHR, 2)
void moe_mma_kernel(const __half* __restrict__ Bw, const float* __restrict__ bias,
                    float* __restrict__ Dout,
                    const float* __restrict__ rawA,   // x fp32 (GEMM1)
                    const float* __restrict__ rawB,   // w1 fp32 (GEMM1)
                    const float4* __restrict__ cvt_src,  // w2 fp32
                    __half2* __restrict__ cvt_dst, size_t cvt_n4) {
    if (SWIGLU && blockIdx.y == 128) {  // w2 conversion CTAs (overlap row)
        size_t i = (size_t)blockIdx.x * NTHR + threadIdx.x;
        const size_t stride = (size_t)gridDim.x * NTHR;
        for (; i < cvt_n4; i += stride) {
            float4 v = cvt_src[i];
            cvt_dst[2 * i] = __floats2half2_rn(v.x, v.y);
            cvt_dst[2 * i + 1] = __floats2half2_rn(v.z, v.w);
        }
        return;
    }

    constexpr int BN = 32 * NT;
    constexpr int STAGE_BYTES = (BM + BN) * LDSH * 2;
    constexpr int BCH = NT;

    extern __shared__ char smem[];
    const uint32_t smem_u = s2u(smem);
    __shared__ int s_chunk;

    const int tid = threadIdx.x;
    const int lane = tid & 31;
    const int warp = tid >> 5;
    const int wm = warp & 1;
    const int wn = warp >> 1;

    const int bn = blockIdx.x, bm = blockIdx.y;
    const int e = bm >> 4;
    const size_t row0 = (size_t)bm * BM;
    const int n0 = bn * BN;
    const int NBROWS = SWIGLU ? 5760 : 2880;

    if (SWIGLU) {
        // cooperative conversion of this CTA's x slab and w1 slab
        convert_slab((const float4*)(rawA + row0 * KDIM),
                     (__half2*)(g_xh + row0 * KDIM), &g_ctr[720 + bm],
                     &g_ctr[848 + bm], tid, &s_chunk);
        const int slab = e * 45 + bn;
        const size_t woff = ((size_t)e * 5760 + n0) * KDIM;
        convert_slab((const float4*)(rawB + woff), (__half2*)(g_w1h + woff),
                     &g_ctr[slab], &g_ctr[360 + slab], tid, &s_chunk);
        if (tid == 0) {
            while (atomicAdd(&g_ctr[848 + bm], 0) < NCHUNK) __nanosleep(100);
            while (atomicAdd(&g_ctr[360 + slab], 0) < NCHUNK) __nanosleep(100);
            __threadfence();
        }
        __syncthreads();
    }

    const __half* Abase = (SWIGLU ? g_xh : g_acth) + row0 * KDIM;
    const __half* Bbase = Bw + (size_t)e * NBROWS * KDIM + (size_t)n0 * KDIM;

    const int crb = tid >> 3;
    const int cc8 = (tid & 7) * 8;
    const __half* Acp = Abase + (size_t)crb * KDIM + cc8;
    const __half* Bcp = Bbase + (size_t)crb * KDIM + cc8;
    const uint32_t sAo = smem_u + (crb * LDSH + cc8) * 2;
    const uint32_t sBo = smem_u + A_BYTES + (crb * LDSH + cc8) * 2;
    const size_t gstep = (size_t)32 * KDIM;
    const uint32_t sstep = 32 * LDSH * 2;

#pragma unroll
    for (int p = 0; p < NSTAGE - 1; p++) {
        const uint32_t sb = p * STAGE_BYTES;
        const int k0 = p * BK;
#pragma unroll
        for (int q = 0; q < 4; q++)
            cp16(sAo + sb + q * sstep, Acp + q * gstep + k0);
#pragma unroll
        for (int q = 0; q < BCH; q++)
            cp16(sBo + sb + q * sstep, Bcp + q * gstep + k0);
        asm volatile("cp.async.commit_group;" ::: "memory");
    }

    float acc[4][NT][4];
#pragma unroll
    for (int i = 0; i < 4; i++)
#pragma unroll
        for (int j = 0; j < NT; j++)
#pragma unroll
            for (int k = 0; k < 4; k++) acc[i][j][k] = 0.0f;

    const uint32_t aOff =
        ((wm * 64 + (lane & 15)) * LDSH + (lane >> 4) * 8) * 2;
    const uint32_t bOff =
        A_BYTES +
        ((wn * (8 * NT) + (lane & 7) + ((lane >> 4) & 1) * 8) * LDSH +
         ((lane >> 3) & 1) * 8) * 2;
    const uint32_t bOff2 =
        A_BYTES +
        ((wn * (8 * NT) + (NT & ~1) * 8 + (lane & 7)) * LDSH +
         ((lane >> 3) & 1) * 8) * 2;

    for (int it = 0; it < NKITER; it++) {
        asm volatile("cp.async.wait_group 1;" ::: "memory");
        __syncthreads();

        const int kf = it + NSTAGE - 1;
        if (kf < NKITER) {
            const uint32_t sb = (kf % NSTAGE) * STAGE_BYTES;
            const int k0 = kf * BK;
#pragma unroll
            for (int q = 0; q < 4; q++)
                cp16(sAo + sb + q * sstep, Acp + q * gstep + k0);
#pragma unroll
            for (int q = 0; q < BCH; q++)
                cp16(sBo + sb + q * sstep, Bcp + q * gstep + k0);
        }
        asm volatile("cp.async.commit_group;" ::: "memory");

        const uint32_t stg = smem_u + (it % NSTAGE) * STAGE_BYTES;
#pragma unroll
        for (int kk = 0; kk < 4; kk++) {
            const uint32_t stA = stg + aOff + kk * 32;
            const uint32_t stB = stg + bOff + kk * 32;
            uint32_t af[4][4], breg[2 * NT];
#pragma unroll
            for (int i = 0; i < 4; i++)
                ldsm_x4(af[i], stA + i * (16 * LDSH * 2));
#pragma unroll
            for (int p = 0; p < NT / 2; p++)
                ldsm_x4(breg + 4 * p, stB + p * (16 * LDSH * 2));
            if (NT & 1)
                ldsm_x2(breg + 2 * (NT - 1), stg + bOff2 + kk * 32);
#pragma unroll
            for (int i = 0; i < 4; i++)
#pragma unroll
                for (int j = 0; j < NT; j++)
                    mma_f16(acc[i][j], af[i], breg + 2 * j);
        }
    }

    // epilogue (register-resident; pairs (2q,2q+1) in c0/c1 and c2/c3)
    const int q2 = 2 * (lane & 3);
    if (SWIGLU) {
        const float* bb = bias + (size_t)e * NBROWS + n0 + wn * (8 * NT);
        __half* actb = g_acth + row0 * 2880 + (size_t)(n0 >> 1) + wn * (4 * NT);
        float2 bj[NT];
#pragma unroll
        for (int j = 0; j < NT; j++) bj[j] = *(const float2*)(bb + j * 8 + q2);
#pragma unroll
        for (int i = 0; i < 4; i++) {
            const int r1 = wm * 64 + i * 16 + (lane >> 2);
#pragma unroll
            for (int j = 0; j < NT; j++) {
                const int hc = j * 4 + (lane & 3);
#pragma unroll
                for (int hrow = 0; hrow < 2; hrow++) {
                    float g = acc[i][j][2 * hrow] + bj[j].x;
                    float l = acc[i][j][2 * hrow + 1] + bj[j].y;
                    g = fminf(g, 7.0f);
                    l = fminf(fmaxf(l, -7.0f), 7.0f);
                    float sg = 1.0f / (1.0f + __expf(-1.702f * g));
                    actb[(size_t)(r1 + 8 * hrow) * 2880 + hc] =
                        __float2half_rn(g * sg * (l + 1.0f));
                }
            }
        }
    } else {
        const float* bb = bias + (size_t)e * NBROWS + n0 + wn * (8 * NT);
        float* ob = Dout + row0 * 2880 + n0 + wn * (8 * NT);
        float2 bj[NT];
#pragma unroll
        for (int j = 0; j < NT; j++) bj[j] = *(const float2*)(bb + j * 8 + q2);
#pragma unroll
        for (int i = 0; i < 4; i++) {
            const int r1 = wm * 64 + i * 16 + (lane >> 2);
#pragma unroll
            for (int j = 0; j < NT; j++) {
                const int oc = j * 8 + q2;
#pragma unroll
                for (int hrow = 0; hrow < 2; hrow++) {
                    float2 v;
                    v.x = acc[i][j][2 * hrow] + bj[j].x;
                    v.y = acc[i][j][2 * hrow + 1] + bj[j].y;
                    *(float2*)(ob + (size_t)(r1 + 8 * hrow) * 2880 + oc) = v;
                }
            }
        }
    }
}

// ---------------------------------------------------------------------------
extern "C" void kernel_launch(void* const* d_in, const int* in_sizes, int n_in,
                              void* d_out, int out_size) {
    const float* x = (const float*)d_in[0];
    const float* w1 = (const float*)d_in[2];
    const float* b1 = (const float*)d_in[3];
    const float* w2 = (const float*)d_in[4];
    const float* b2 = (const float*)d_in[5];
    float* out = (float*)d_out;

    constexpr int SM1 = NSTAGE * (BM + 128) * LDSH * 2;  // 110592
    constexpr int SM2 = NSTAGE * (BM + 96) * LDSH * 2;   //  96768
    cudaFuncSetAttribute(moe_mma_kernel<true, 4>,
                         cudaFuncAttributeMaxDynamicSharedMemorySize, SM1);
    cudaFuncSetAttribute(moe_mma_kernel<false, 3>,
                         cudaFuncAttributeMaxDynamicSharedMemorySize, SM2);

    __half *gw1h, *gw2h;
    cudaGetSymbolAddress((void**)&gw1h, g_w1h);
    cudaGetSymbolAddress((void**)&gw2h, g_w2h);
    const size_t nw2 = (size_t)8 * 2880 * 2880 / 4;

    reset_counters_kernel<<<1, 1024>>>();
    // GEMM1 (+ in-kernel x/w1 conversion + overlapped w2 conversion row)
    moe_mma_kernel<true, 4><<<dim3(45, 129), NTHR, SM1>>>(
        gw1h, b1, nullptr, x, w1, (const float4*)w2, (__half2*)gw2h, nw2);
    // GEMM2
    moe_mma_kernel<false, 3><<<dim3(30, 128), NTHR, SM2>>>(
        gw2h, b2, out, nullptr, nullptr, nullptr, nullptr, 0);
}

// round 15
// speedup vs baseline: 1.0816x; 1.0816x over previous
#include <cuda_runtime.h>
#include <cuda_fp16.h>
#include <cstdint>

// ---------------------------------------------------------------------------
// T=16384, D=H=2880, E=8, C=2048, N1=5760. K=2880 both GEMMs.
// fp16 mma.sync m16n8k16 (fp32 acc), 2 CTAs/SM, cp.async 3-stage pipeline
// with one __syncthreads per K-iter (R10 skeleton = best known).
// w2 fp32->fp16 conversion rides inside GEMM1's grid (idle-DRAM overlap);
// x and w1 conversions merged into a single prepass launch.
// ---------------------------------------------------------------------------
#define KDIM 2880
#define BM 128
#define BK 64              // halves per k-stage (128 B rows)
#define NSTAGE 3
#define NKITER 45          // 2880/64
#define LDSH 72            // smem pitch in halves (64 + 8 pad) = 144 B
#define A_BYTES (BM * LDSH * 2)  // 18432
#define NTHR 256

__device__ __half g_xh[(size_t)16384 * 2880];
__device__ __half g_w1h[(size_t)8 * 5760 * 2880];
__device__ __half g_w2h[(size_t)8 * 2880 * 2880];
__device__ __half g_acth[(size_t)16384 * 2880];

__device__ __forceinline__ uint32_t s2u(const void* p) {
    uint32_t a;
    asm("{.reg .u64 t; cvta.to.shared.u64 t, %1; cvt.u32.u64 %0, t;}"
        : "=r"(a) : "l"(p));
    return a;
}
__device__ __forceinline__ void cp16(uint32_t dst, const void* src) {
    asm volatile("cp.async.cg.shared.global [%0], [%1], 16;" ::"r"(dst),
                 "l"(src) : "memory");
}
__device__ __forceinline__ void ldsm_x4(uint32_t* r, uint32_t addr) {
    asm volatile(
        "ldmatrix.sync.aligned.m8n8.x4.shared.b16 {%0,%1,%2,%3}, [%4];"
        : "=r"(r[0]), "=r"(r[1]), "=r"(r[2]), "=r"(r[3]) : "r"(addr));
}
__device__ __forceinline__ void ldsm_x2(uint32_t* r, uint32_t addr) {
    asm volatile(
        "ldmatrix.sync.aligned.m8n8.x2.shared.b16 {%0,%1}, [%2];"
        : "=r"(r[0]), "=r"(r[1]) : "r"(addr));
}
__device__ __forceinline__ void mma_f16(float* c, const uint32_t* a,
                                        const uint32_t* b) {
    asm volatile(
        "mma.sync.aligned.m16n8k16.row.col.f32.f16.f16.f32 "
        "{%0,%1,%2,%3}, {%4,%5,%6,%7}, {%8,%9}, {%0,%1,%2,%3};"
        : "+f"(c[0]), "+f"(c[1]), "+f"(c[2]), "+f"(c[3])
        : "r"(a[0]), "r"(a[1]), "r"(a[2]), "r"(a[3]), "r"(b[0]), "r"(b[1]));
}

// Merged x + w1 conversion: one launch, two segments.
__global__ void cvt_xw1_kernel(const float4* __restrict__ xs, __half2* xd,
                               size_t nx4, const float4* __restrict__ ws,
                               __half2* wd, size_t nw4) {
    size_t i = (size_t)blockIdx.x * blockDim.x + threadIdx.x;
    const size_t stride = (size_t)gridDim.x * blockDim.x;
    for (size_t k = i; k < nx4; k += stride) {
        float4 v = xs[k];
        xd[2 * k] = __floats2half2_rn(v.x, v.y);
        xd[2 * k + 1] = __floats2half2_rn(v.z, v.w);
    }
    for (size_t k = i; k < nw4; k += stride) {
        float4 v = ws[k];
        wd[2 * k] = __floats2half2_rn(v.x, v.y);
        wd[2 * k + 1] = __floats2half2_rn(v.z, v.w);
    }
}

// ---------------------------------------------------------------------------
// NT = n8-subtiles per warp. BN = 32*NT. NT=4 -> 128 (GEMM1), 3 -> 96 (GEMM2)
// GEMM1 carries an extra blockIdx.y row (==128) that converts w2 -> fp16.
// ---------------------------------------------------------------------------
template <bool SWIGLU, int NT>
__global__ __launch_bounds__(NTHR, 2)
void moe_mma_kernel(const __half* __restrict__ Bw, const float* __restrict__ bias,
                    float* __restrict__ Dout,
                    const float4* __restrict__ cvt_src,
                    __half2* __restrict__ cvt_dst, size_t cvt_n4) {
    if (SWIGLU && blockIdx.y == 128) {  // w2 conversion CTAs (overlap row)
        size_t i = (size_t)blockIdx.x * NTHR + threadIdx.x;
        const size_t stride = (size_t)gridDim.x * NTHR;
        for (; i < cvt_n4; i += stride) {
            float4 v = cvt_src[i];
            cvt_dst[2 * i] = __floats2half2_rn(v.x, v.y);
            cvt_dst[2 * i + 1] = __floats2half2_rn(v.z, v.w);
        }
        return;
    }

    constexpr int BN = 32 * NT;
    constexpr int STAGE_BYTES = (BM + BN) * LDSH * 2;
    constexpr int BCH = NT;

    extern __shared__ char smem[];
    const uint32_t smem_u = s2u(smem);

    const int tid = threadIdx.x;
    const int lane = tid & 31;
    const int warp = tid >> 5;
    const int wm = warp & 1;   // 2 warps along M (64 rows)
    const int wn = warp >> 1;  // 4 warps along N

    const int bn = blockIdx.x, bm = blockIdx.y;
    const int e = bm >> 4;
    const size_t row0 = (size_t)bm * BM;
    const int n0 = bn * BN;
    const int NBROWS = SWIGLU ? 5760 : 2880;

    const __half* Abase = (SWIGLU ? g_xh : g_acth) + row0 * KDIM;
    const __half* Bbase = Bw + (size_t)e * NBROWS * KDIM + (size_t)n0 * KDIM;

    const int crb = tid >> 3;
    const int cc8 = (tid & 7) * 8;
    const __half* Acp = Abase + (size_t)crb * KDIM + cc8;
    const __half* Bcp = Bbase + (size_t)crb * KDIM + cc8;
    const uint32_t sAo = smem_u + (crb * LDSH + cc8) * 2;
    const uint32_t sBo = smem_u + A_BYTES + (crb * LDSH + cc8) * 2;
    const size_t gstep = (size_t)32 * KDIM;
    const uint32_t sstep = 32 * LDSH * 2;

#pragma unroll
    for (int p = 0; p < NSTAGE - 1; p++) {
        const uint32_t sb = p * STAGE_BYTES;
        const int k0 = p * BK;
#pragma unroll
        for (int q = 0; q < 4; q++)
            cp16(sAo + sb + q * sstep, Acp + q * gstep + k0);
#pragma unroll
        for (int q = 0; q < BCH; q++)
            cp16(sBo + sb + q * sstep, Bcp + q * gstep + k0);
        asm volatile("cp.async.commit_group;" ::: "memory");
    }

    float acc[4][NT][4];
#pragma unroll
    for (int i = 0; i < 4; i++)
#pragma unroll
        for (int j = 0; j < NT; j++)
#pragma unroll
            for (int k = 0; k < 4; k++) acc[i][j][k] = 0.0f;

    const uint32_t aOff =
        ((wm * 64 + (lane & 15)) * LDSH + (lane >> 4) * 8) * 2;
    const uint32_t bOff =
        A_BYTES +
        ((wn * (8 * NT) + (lane & 7) + ((lane >> 4) & 1) * 8) * LDSH +
         ((lane >> 3) & 1) * 8) * 2;
    const uint32_t bOff2 =
        A_BYTES +
        ((wn * (8 * NT) + (NT & ~1) * 8 + (lane & 7)) * LDSH +
         ((lane >> 3) & 1) * 8) * 2;

    for (int it = 0; it < NKITER; it++) {
        asm volatile("cp.async.wait_group 1;" ::: "memory");
        __syncthreads();

        const int kf = it + NSTAGE - 1;
        if (kf < NKITER) {
            const uint32_t sb = (kf % NSTAGE) * STAGE_BYTES;
            const int k0 = kf * BK;
#pragma unroll
            for (int q = 0; q < 4; q++)
                cp16(sAo + sb + q * sstep, Acp + q * gstep + k0);
#pragma unroll
            for (int q = 0; q < BCH; q++)
                cp16(sBo + sb + q * sstep, Bcp + q * gstep + k0);
        }
        asm volatile("cp.async.commit_group;" ::: "memory");

        const uint32_t stg = smem_u + (it % NSTAGE) * STAGE_BYTES;
#pragma unroll
        for (int kk = 0; kk < 4; kk++) {
            const uint32_t stA = stg + aOff + kk * 32;
            const uint32_t stB = stg + bOff + kk * 32;
            uint32_t af[4][4], breg[2 * NT];
#pragma unroll
            for (int i = 0; i < 4; i++)
                ldsm_x4(af[i], stA + i * (16 * LDSH * 2));
#pragma unroll
            for (int p = 0; p < NT / 2; p++)
                ldsm_x4(breg + 4 * p, stB + p * (16 * LDSH * 2));
            if (NT & 1)
                ldsm_x2(breg + 2 * (NT - 1), stg + bOff2 + kk * 32);
#pragma unroll
            for (int i = 0; i < 4; i++)
#pragma unroll
                for (int j = 0; j < NT; j++)
                    mma_f16(acc[i][j], af[i], breg + 2 * j);
        }
    }

    // epilogue (register-resident; pairs (2q,2q+1) in c0/c1 and c2/c3)
    const int q2 = 2 * (lane & 3);
    if (SWIGLU) {
        const float* bb = bias + (size_t)e * NBROWS + n0 + wn * (8 * NT);
        __half* actb = g_acth + row0 * 2880 + (size_t)(n0 >> 1) + wn * (4 * NT);
        float2 bj[NT];
#pragma unroll
        for (int j = 0; j < NT; j++) bj[j] = *(const float2*)(bb + j * 8 + q2);
#pragma unroll
        for (int i = 0; i < 4; i++) {
            const int r1 = wm * 64 + i * 16 + (lane >> 2);
#pragma unroll
            for (int j = 0; j < NT; j++) {
                const int hc = j * 4 + (lane & 3);
#pragma unroll
                for (int hrow = 0; hrow < 2; hrow++) {
                    float g = acc[i][j][2 * hrow] + bj[j].x;
                    float l = acc[i][j][2 * hrow + 1] + bj[j].y;
                    g = fminf(g, 7.0f);
                    l = fminf(fmaxf(l, -7.0f), 7.0f);
                    float sg = 1.0f / (1.0f + __expf(-1.702f * g));
                    actb[(size_t)(r1 + 8 * hrow) * 2880 + hc] =
                        __float2half_rn(g * sg * (l + 1.0f));
                }
            }
        }
    } else {
        const float* bb = bias + (size_t)e * NBROWS + n0 + wn * (8 * NT);
        float* ob = Dout + row0 * 2880 + n0 + wn * (8 * NT);
        float2 bj[NT];
#pragma unroll
        for (int j = 0; j < NT; j++) bj[j] = *(const float2*)(bb + j * 8 + q2);
#pragma unroll
        for (int i = 0; i < 4; i++) {
            const int r1 = wm * 64 + i * 16 + (lane >> 2);
#pragma unroll
            for (int j = 0; j < NT; j++) {
                const int oc = j * 8 + q2;
#pragma unroll
                for (int hrow = 0; hrow < 2; hrow++) {
                    float2 v;
                    v.x = acc[i][j][2 * hrow] + bj[j].x;
                    v.y = acc[i][j][2 * hrow + 1] + bj[j].y;
                    *(float2*)(ob + (size_t)(r1 + 8 * hrow) * 2880 + oc) = v;
                }
            }
        }
    }
}

// ---------------------------------------------------------------------------
extern "C" void kernel_launch(void* const* d_in, const int* in_sizes, int n_in,
                              void* d_out, int out_size) {
    const float* x = (const float*)d_in[0];
    const float* w1 = (const float*)d_in[2];
    const float* b1 = (const float*)d_in[3];
    const float* w2 = (const float*)d_in[4];
    const float* b2 = (const float*)d_in[5];
    float* out = (float*)d_out;

    constexpr int SM1 = NSTAGE * (BM + 128) * LDSH * 2;  // 110592
    constexpr int SM2 = NSTAGE * (BM + 96) * LDSH * 2;   //  96768
    cudaFuncSetAttribute(moe_mma_kernel<true, 4>,
                         cudaFuncAttributeMaxDynamicSharedMemorySize, SM1);
    cudaFuncSetAttribute(moe_mma_kernel<false, 3>,
                         cudaFuncAttributeMaxDynamicSharedMemorySize, SM2);

    __half *gxh, *gw1h, *gw2h;
    cudaGetSymbolAddress((void**)&gxh, g_xh);
    cudaGetSymbolAddress((void**)&gw1h, g_w1h);
    cudaGetSymbolAddress((void**)&gw2h, g_w2h);

    const size_t nx = (size_t)16384 * 2880 / 4;
    const size_t nw1 = (size_t)8 * 5760 * 2880 / 4;
    const size_t nw2 = (size_t)8 * 2880 * 2880 / 4;

    // merged x + w1 conversion (one launch)
    cvt_xw1_kernel<<<4096, 256>>>((const float4*)x, (__half2*)gxh, nx,
                                  (const float4*)w1, (__half2*)gw1h, nw1);

    // GEMM1 (+ overlapped w2 conversion row)
    moe_mma_kernel<true, 4><<<dim3(45, 129), NTHR, SM1>>>(
        gw1h, b1, nullptr, (const float4*)w2, (__half2*)gw2h, nw2);
    // GEMM2
    moe_mma_kernel<false, 3><<<dim3(30, 128), NTHR, SM2>>>(
        gw2h, b2, out, nullptr, nullptr, 0);
}

// round 16
// speedup vs baseline: 1.3260x; 1.2259x over previous
#include <cuda_runtime.h>
#include <cuda_fp16.h>
#include <cstdint>

// ---------------------------------------------------------------------------
// T=16384, D=H=2880, E=8, C=2048, N1=5760. K=2880 both GEMMs.
// fp16 mma.sync m16n8k16 (fp32 acc), 2 CTAs/SM, cp.async 3-stage pipeline,
// one __syncthreads per K-iter (R10 skeleton = best known).
// w2 fp32->fp16 conversion rides in GEMM1's grid as blockIdx.y==0 (FIRST
// wave, so it overlaps the GEMM instead of tailing it). x+w1 in one prepass.
// ---------------------------------------------------------------------------
#define KDIM 2880
#define BM 128
#define BK 64              // halves per k-stage (128 B rows)
#define NSTAGE 3
#define NKITER 45          // 2880/64
#define LDSH 72            // smem pitch in halves (64 + 8 pad) = 144 B
#define A_BYTES (BM * LDSH * 2)  // 18432
#define NTHR 256

__device__ __half g_xh[(size_t)16384 * 2880];
__device__ __half g_w1h[(size_t)8 * 5760 * 2880];
__device__ __half g_w2h[(size_t)8 * 2880 * 2880];
__device__ __half g_acth[(size_t)16384 * 2880];

__device__ __forceinline__ uint32_t s2u(const void* p) {
    uint32_t a;
    asm("{.reg .u64 t; cvta.to.shared.u64 t, %1; cvt.u32.u64 %0, t;}"
        : "=r"(a) : "l"(p));
    return a;
}
__device__ __forceinline__ void cp16(uint32_t dst, const void* src) {
    asm volatile("cp.async.cg.shared.global [%0], [%1], 16;" ::"r"(dst),
                 "l"(src) : "memory");
}
__device__ __forceinline__ void ldsm_x4(uint32_t* r, uint32_t addr) {
    asm volatile(
        "ldmatrix.sync.aligned.m8n8.x4.shared.b16 {%0,%1,%2,%3}, [%4];"
        : "=r"(r[0]), "=r"(r[1]), "=r"(r[2]), "=r"(r[3]) : "r"(addr));
}
__device__ __forceinline__ void ldsm_x2(uint32_t* r, uint32_t addr) {
    asm volatile(
        "ldmatrix.sync.aligned.m8n8.x2.shared.b16 {%0,%1}, [%2];"
        : "=r"(r[0]), "=r"(r[1]) : "r"(addr));
}
__device__ __forceinline__ void mma_f16(float* c, const uint32_t* a,
                                        const uint32_t* b) {
    asm volatile(
        "mma.sync.aligned.m16n8k16.row.col.f32.f16.f16.f32 "
        "{%0,%1,%2,%3}, {%4,%5,%6,%7}, {%8,%9}, {%0,%1,%2,%3};"
        : "+f"(c[0]), "+f"(c[1]), "+f"(c[2]), "+f"(c[3])
        : "r"(a[0]), "r"(a[1]), "r"(a[2]), "r"(a[3]), "r"(b[0]), "r"(b[1]));
}

// Merged x + w1 conversion: one launch, two segments.
__global__ void cvt_xw1_kernel(const float4* __restrict__ xs, __half2* xd,
                               size_t nx4, const float4* __restrict__ ws,
                               __half2* wd, size_t nw4) {
    size_t i = (size_t)blockIdx.x * blockDim.x + threadIdx.x;
    const size_t stride = (size_t)gridDim.x * blockDim.x;
    for (size_t k = i; k < nx4; k += stride) {
        float4 v = xs[k];
        xd[2 * k] = __floats2half2_rn(v.x, v.y);
        xd[2 * k + 1] = __floats2half2_rn(v.z, v.w);
    }
    for (size_t k = i; k < nw4; k += stride) {
        float4 v = ws[k];
        wd[2 * k] = __floats2half2_rn(v.x, v.y);
        wd[2 * k + 1] = __floats2half2_rn(v.z, v.w);
    }
}

// ---------------------------------------------------------------------------
// NT = n8-subtiles per warp. BN = 32*NT. NT=4 -> 128 (GEMM1), 3 -> 96 (GEMM2)
// GEMM1: blockIdx.y==0 row converts w2 -> fp16 (first wave, overlapped);
// GEMM rows are blockIdx.y-1.
// ---------------------------------------------------------------------------
template <bool SWIGLU, int NT>
__global__ __launch_bounds__(NTHR, 2)
void moe_mma_kernel(const __half* __restrict__ Bw, const float* __restrict__ bias,
                    float* __restrict__ Dout,
                    const float4* __restrict__ cvt_src,
                    __half2* __restrict__ cvt_dst, size_t cvt_n4) {
    if (SWIGLU && blockIdx.y == 0) {  // w2 conversion CTAs (FIRST wave)
        size_t i = (size_t)blockIdx.x * NTHR + threadIdx.x;
        const size_t stride = (size_t)gridDim.x * NTHR;
        for (; i < cvt_n4; i += stride) {
            float4 v = cvt_src[i];
            cvt_dst[2 * i] = __floats2half2_rn(v.x, v.y);
            cvt_dst[2 * i + 1] = __floats2half2_rn(v.z, v.w);
        }
        return;
    }

    constexpr int BN = 32 * NT;
    constexpr int STAGE_BYTES = (BM + BN) * LDSH * 2;
    constexpr int BCH = NT;

    extern __shared__ char smem[];
    const uint32_t smem_u = s2u(smem);

    const int tid = threadIdx.x;
    const int lane = tid & 31;
    const int warp = tid >> 5;
    const int wm = warp & 1;   // 2 warps along M (64 rows)
    const int wn = warp >> 1;  // 4 warps along N

    const int bn = blockIdx.x;
    const int bm = SWIGLU ? (blockIdx.y - 1) : blockIdx.y;
    const int e = bm >> 4;
    const size_t row0 = (size_t)bm * BM;
    const int n0 = bn * BN;
    const int NBROWS = SWIGLU ? 5760 : 2880;

    const __half* Abase = (SWIGLU ? g_xh : g_acth) + row0 * KDIM;
    const __half* Bbase = Bw + (size_t)e * NBROWS * KDIM + (size_t)n0 * KDIM;

    const int crb = tid >> 3;
    const int cc8 = (tid & 7) * 8;
    const __half* Acp = Abase + (size_t)crb * KDIM + cc8;
    const __half* Bcp = Bbase + (size_t)crb * KDIM + cc8;
    const uint32_t sAo = smem_u + (crb * LDSH + cc8) * 2;
    const uint32_t sBo = smem_u + A_BYTES + (crb * LDSH + cc8) * 2;
    const size_t gstep = (size_t)32 * KDIM;
    const uint32_t sstep = 32 * LDSH * 2;

#pragma unroll
    for (int p = 0; p < NSTAGE - 1; p++) {
        const uint32_t sb = p * STAGE_BYTES;
        const int k0 = p * BK;
#pragma unroll
        for (int q = 0; q < 4; q++)
            cp16(sAo + sb + q * sstep, Acp + q * gstep + k0);
#pragma unroll
        for (int q = 0; q < BCH; q++)
            cp16(sBo + sb + q * sstep, Bcp + q * gstep + k0);
        asm volatile("cp.async.commit_group;" ::: "memory");
    }

    float acc[4][NT][4];
#pragma unroll
    for (int i = 0; i < 4; i++)
#pragma unroll
        for (int j = 0; j < NT; j++)
#pragma unroll
            for (int k = 0; k < 4; k++) acc[i][j][k] = 0.0f;

    const uint32_t aOff =
        ((wm * 64 + (lane & 15)) * LDSH + (lane >> 4) * 8) * 2;
    const uint32_t bOff =
        A_BYTES +
        ((wn * (8 * NT) + (lane & 7) + ((lane >> 4) & 1) * 8) * LDSH +
         ((lane >> 3) & 1) * 8) * 2;
    const uint32_t bOff2 =
        A_BYTES +
        ((wn * (8 * NT) + (NT & ~1) * 8 + (lane & 7)) * LDSH +
         ((lane >> 3) & 1) * 8) * 2;

    for (int it = 0; it < NKITER; it++) {
        asm volatile("cp.async.wait_group 1;" ::: "memory");
        __syncthreads();

        const int kf = it + NSTAGE - 1;
        if (kf < NKITER) {
            const uint32_t sb = (kf % NSTAGE) * STAGE_BYTES;
            const int k0 = kf * BK;
#pragma unroll
            for (int q = 0; q < 4; q++)
                cp16(sAo + sb + q * sstep, Acp + q * gstep + k0);
#pragma unroll
            for (int q = 0; q < BCH; q++)
                cp16(sBo + sb + q * sstep, Bcp + q * gstep + k0);
        }
        asm volatile("cp.async.commit_group;" ::: "memory");

        const uint32_t stg = smem_u + (it % NSTAGE) * STAGE_BYTES;
#pragma unroll
        for (int kk = 0; kk < 4; kk++) {
            const uint32_t stA = stg + aOff + kk * 32;
            const uint32_t stB = stg + bOff + kk * 32;
            uint32_t af[4][4], breg[2 * NT];
#pragma unroll
            for (int i = 0; i < 4; i++)
                ldsm_x4(af[i], stA + i * (16 * LDSH * 2));
#pragma unroll
            for (int p = 0; p < NT / 2; p++)
                ldsm_x4(breg + 4 * p, stB + p * (16 * LDSH * 2));
            if (NT & 1)
                ldsm_x2(breg + 2 * (NT - 1), stg + bOff2 + kk * 32);
#pragma unroll
            for (int i = 0; i < 4; i++)
#pragma unroll
                for (int j = 0; j < NT; j++)
                    mma_f16(acc[i][j], af[i], breg + 2 * j);
        }
    }

    // epilogue (register-resident; pairs (2q,2q+1) in c0/c1 and c2/c3)
    const int q2 = 2 * (lane & 3);
    if (SWIGLU) {
        const float* bb = bias + (size_t)e * NBROWS + n0 + wn * (8 * NT);
        __half* actb = g_acth + row0 * 2880 + (size_t)(n0 >> 1) + wn * (4 * NT);
        float2 bj[NT];
#pragma unroll
        for (int j = 0; j < NT; j++) bj[j] = *(const float2*)(bb + j * 8 + q2);
#pragma unroll
        for (int i = 0; i < 4; i++) {
            const int r1 = wm * 64 + i * 16 + (lane >> 2);
#pragma unroll
            for (int j = 0; j < NT; j++) {
                const int hc = j * 4 + (lane & 3);
#pragma unroll
                for (int hrow = 0; hrow < 2; hrow++) {
                    float g = acc[i][j][2 * hrow] + bj[j].x;
                    float l = acc[i][j][2 * hrow + 1] + bj[j].y;
                    g = fminf(g, 7.0f);
                    l = fminf(fmaxf(l, -7.0f), 7.0f);
                    float sg = 1.0f / (1.0f + __expf(-1.702f * g));
                    actb[(size_t)(r1 + 8 * hrow) * 2880 + hc] =
                        __float2half_rn(g * sg * (l + 1.0f));
                }
            }
        }
    } else {
        const float* bb = bias + (size_t)e * NBROWS + n0 + wn * (8 * NT);
        float* ob = Dout + row0 * 2880 + n0 + wn * (8 * NT);
        float2 bj[NT];
#pragma unroll
        for (int j = 0; j < NT; j++) bj[j] = *(const float2*)(bb + j * 8 + q2);
#pragma unroll
        for (int i = 0; i < 4; i++) {
            const int r1 = wm * 64 + i * 16 + (lane >> 2);
#pragma unroll
            for (int j = 0; j < NT; j++) {
                const int oc = j * 8 + q2;
#pragma unroll
                for (int hrow = 0; hrow < 2; hrow++) {
                    float2 v;
                    v.x = acc[i][j][2 * hrow] + bj[j].x;
                    v.y = acc[i][j][2 * hrow + 1] + bj[j].y;
                    *(float2*)(ob + (size_t)(r1 + 8 * hrow) * 2880 + oc) = v;
                }
            }
        }
    }
}

// ---------------------------------------------------------------------------
extern "C" void kernel_launch(void* const* d_in, const int* in_sizes, int n_in,
                              void* d_out, int out_size) {
    const float* x = (const float*)d_in[0];
    const float* w1 = (const float*)d_in[2];
    const float* b1 = (const float*)d_in[3];
    const float* w2 = (const float*)d_in[4];
    const float* b2 = (const float*)d_in[5];
    float* out = (float*)d_out;

    constexpr int SM1 = NSTAGE * (BM + 128) * LDSH * 2;  // 110592
    constexpr int SM2 = NSTAGE * (BM + 96) * LDSH * 2;   //  96768
    cudaFuncSetAttribute(moe_mma_kernel<true, 4>,
                         cudaFuncAttributeMaxDynamicSharedMemorySize, SM1);
    cudaFuncSetAttribute(moe_mma_kernel<false, 3>,
                         cudaFuncAttributeMaxDynamicSharedMemorySize, SM2);

    __half *gxh, *gw1h, *gw2h;
    cudaGetSymbolAddress((void**)&gxh, g_xh);
    cudaGetSymbolAddress((void**)&gw1h, g_w1h);
    cudaGetSymbolAddress((void**)&gw2h, g_w2h);

    const size_t nx = (size_t)16384 * 2880 / 4;
    const size_t nw1 = (size_t)8 * 5760 * 2880 / 4;
    const size_t nw2 = (size_t)8 * 2880 * 2880 / 4;

    // merged x + w1 conversion (one launch)
    cvt_xw1_kernel<<<4096, 256>>>((const float4*)x, (__half2*)gxh, nx,
                                  (const float4*)w1, (__half2*)gw1h, nw1);

    // GEMM1: row 0 = overlapped w2 conversion; rows 1..128 = GEMM m-tiles
    moe_mma_kernel<true, 4><<<dim3(45, 129), NTHR, SM1>>>(
        gw1h, b1, nullptr, (const float4*)w2, (__half2*)gw2h, nw2);
    // GEMM2
    moe_mma_kernel<false, 3><<<dim3(30, 128), NTHR, SM2>>>(
        gw2h, b2, out, nullptr, nullptr, 0);
}